// round 3
// baseline (speedup 1.0000x reference)
#include <cuda_runtime.h>
#include <cstdint>

// Reference math reduces to an all-zero output:
//   probs = one-hot at basis-state 0; gather indices 1<<q never hit index 0
//   -> projected features are exactly 0 -> p1 @ p2^T == 0.
// Kernel = pure 256 MB zero-fill of d_out (float32 8192x8192). HBM-write-bound.
//
// R1 (1 store/thread, 65536 blocks): 36.9us kernel = 7.27 TB/s effective (~91% spec).
// R2 (16 stores/thread grid-stride + __stcs): regressed to 38.8us.
// R3: 2 contiguous float4 stores/thread, 32768 blocks, default cache policy.

__global__ void zero_fill2(float4* __restrict__ out) {
    size_t i = ((size_t)blockIdx.x * blockDim.x + threadIdx.x) * 2;
    const float4 z = make_float4(0.0f, 0.0f, 0.0f, 0.0f);
    out[i]     = z;
    out[i + 1] = z;
}

__global__ void zero_fill_generic(float* __restrict__ out, size_t n) {
    size_t stride = (size_t)gridDim.x * blockDim.x;
    for (size_t i = (size_t)blockIdx.x * blockDim.x + threadIdx.x; i < n;
         i += stride)
        out[i] = 0.0f;
}

extern "C" void kernel_launch(void* const* d_in, const int* in_sizes, int n_in,
                              void* d_out, int out_size) {
    (void)d_in; (void)in_sizes; (void)n_in;

    float* out = (float*)d_out;
    size_t n  = (size_t)out_size;   // 67,108,864 floats
    size_t n4 = n / 4;              // 16,777,216 float4

    const int threads = 256;
    const size_t per_block = (size_t)threads * 2;   // 512 float4 per block

    if ((n % 4 == 0) && (n4 % per_block == 0)) {
        unsigned blocks = (unsigned)(n4 / per_block);   // 32768
        zero_fill2<<<blocks, threads>>>((float4*)out);
    } else {
        // generic fallback for any other shape
        unsigned blocks = 8192;
        zero_fill_generic<<<blocks, 512>>>(out, n);
    }
}

// round 4
// speedup vs baseline: 1.3742x; 1.3742x over previous
#include <cuda_runtime.h>
#include <cstdint>

// Reference math reduces to an all-zero output:
//   probs = one-hot at basis-state 0; gather indices 1<<q never hit index 0
//   -> projected features are exactly 0 -> p1 @ p2^T == 0.
// Kernel = pure 256 MB zero-fill of d_out (float32 8192x8192). HBM-write-bound.
//
// R1: 1 coalesced store/thread, 65536 blocks -> 36.9us kernel (7.27 TB/s).
// R2: 16-deep grid-stride + __stcs -> 38.8us (worse).
// R3: thread-adjacent 2 stores (stride-2 lanes, DE-COALESCED) -> 52.6us.
// R4: 2 BLOCK-CONTIGUOUS coalesced stores/thread:
//     store at [base+tid] and [base+blockDim+tid] — every STG.128 fully
//     coalesced, half the CTAs of R1.

__global__ void zero_fill2c(float4* __restrict__ out) {
    size_t base = (size_t)blockIdx.x * (blockDim.x * 2);
    size_t i = base + threadIdx.x;
    const float4 z = make_float4(0.0f, 0.0f, 0.0f, 0.0f);
    out[i] = z;
    out[i + blockDim.x] = z;
}

__global__ void zero_fill_generic(float* __restrict__ out, size_t n) {
    size_t stride = (size_t)gridDim.x * blockDim.x;
    for (size_t i = (size_t)blockIdx.x * blockDim.x + threadIdx.x; i < n;
         i += stride)
        out[i] = 0.0f;
}

extern "C" void kernel_launch(void* const* d_in, const int* in_sizes, int n_in,
                              void* d_out, int out_size) {
    (void)d_in; (void)in_sizes; (void)n_in;

    float* out = (float*)d_out;
    size_t n  = (size_t)out_size;   // 67,108,864 floats
    size_t n4 = n / 4;              // 16,777,216 float4

    const int threads = 256;
    const size_t per_block = (size_t)threads * 2;   // 512 float4 per block

    if ((n % 4 == 0) && (n4 % per_block == 0)) {
        unsigned blocks = (unsigned)(n4 / per_block);   // 32768
        zero_fill2c<<<blocks, threads>>>((float4*)out);
    } else {
        unsigned blocks = 8192;
        zero_fill_generic<<<blocks, 512>>>(out, n);
    }
}